// round 3
// baseline (speedup 1.0000x reference)
#include <cuda_runtime.h>

// Problem constants (fixed by the dataset)
#define T_LEN   2048
#define Dh      64
#define Hh      8
#define Bb      2
#define BHn     16          // Bb * Hh
#define STATE   512         // Hh * Dh
#define BM      64          // dest rows per CTA
#define BN      64          // key tile
#define SSTR    68          // smem row stride (floats), 16B-aligned rows
#define NTHREADS 128

// Scratch: attention output in [B, T, H*Dh] layout (8 MB)
__device__ float g_attn[(size_t)Bb * T_LEN * STATE];

// ---------------------------------------------------------------------------
// Attention kernel: flash-style online softmax, fp32 CUDA cores.
// Grid: (T/BM, BH). 128 threads = 16x8 layout; each thread owns a 4x8 microtile.
// ---------------------------------------------------------------------------
__global__ void attn_kernel(const float* __restrict__ q,
                            const float* __restrict__ k,
                            const float* __restrict__ v,
                            const int* __restrict__ lenmask)   // int32 bool: 1 = padded
{
    extern __shared__ __align__(16) float sm[];
    float* q_sh = sm;                       // [BM][SSTR]
    float* k_sh = q_sh + BM * SSTR;         // [BN][SSTR]
    float* v_sh = k_sh + BN * SSTR;         // [BN][SSTR]
    float* p_sh = v_sh + BN * SSTR;         // [BM][SSTR]
    __shared__ int sh_len;

    const int tid = threadIdx.x;
    const int bh  = blockIdx.y;
    const int b   = bh >> 3;                // H = 8
    const int h   = bh & 7;
    const int m0  = blockIdx.x * BM;

    // ---- per-batch valid length: L = count of zeros in src_length_mask[b] ----
    if (tid == 0) sh_len = 0;
    __syncthreads();
    {
        int cnt = 0;
        const int* lm = lenmask + (size_t)b * T_LEN;
        for (int s = tid; s < T_LEN; s += NTHREADS) cnt += (lm[s] == 0);
        cnt += __shfl_xor_sync(0xffffffffu, cnt, 1);
        cnt += __shfl_xor_sync(0xffffffffu, cnt, 2);
        cnt += __shfl_xor_sync(0xffffffffu, cnt, 4);
        cnt += __shfl_xor_sync(0xffffffffu, cnt, 8);
        cnt += __shfl_xor_sync(0xffffffffu, cnt, 16);
        if ((tid & 31) == 0) atomicAdd(&sh_len, cnt);
    }

    // ---- load Q tile (once) ----
    {
        const float4* qb = (const float4*)(q + ((size_t)bh * T_LEN + m0) * Dh);
        for (int i = tid; i < BM * (Dh / 4); i += NTHREADS) {
            const int r = i >> 4, c = i & 15;
            *(float4*)&q_sh[r * SSTR + c * 4] = qb[r * 16 + c];
        }
    }
    __syncthreads();
    const int L = sh_len;

    const int tr = tid >> 3;        // 0..15
    const int tc = tid & 7;         // 0..7
    const int row_base = tr * 4;
    const int col_base = tc * 8;

    float m_i[4], l_i[4], acc[4][8];
#pragma unroll
    for (int i = 0; i < 4; i++) {
        m_i[i] = -1e30f; l_i[i] = 0.f;
#pragma unroll
        for (int j = 0; j < 8; j++) acc[i][j] = 0.f;
    }

    const float scale = 0.125f;     // 1/sqrt(64)
    const int s_hi = m0 + BM;       // causal cap (<= T_LEN)

    for (int s0 = 0; s0 < s_hi; s0 += BN) {
        if (s0 >= L) break;         // fully length-masked tile (uniform per batch)
        __syncthreads();            // protect k/v/p smem vs previous iteration

        // ---- load K, V tiles ----
        {
            const float4* kb = (const float4*)(k + ((size_t)bh * T_LEN + s0) * Dh);
            const float4* vb = (const float4*)(v + ((size_t)bh * T_LEN + s0) * Dh);
            for (int i = tid; i < BN * (Dh / 4); i += NTHREADS) {
                const int r = i >> 4, c = i & 15;
                *(float4*)&k_sh[r * SSTR + c * 4] = kb[r * 16 + c];
                *(float4*)&v_sh[r * SSTR + c * 4] = vb[r * 16 + c];
            }
        }
        __syncthreads();

        // ---- S = Q K^T, 4x8 microtile per thread ----
        float s_reg[4][8];
#pragma unroll
        for (int i = 0; i < 4; i++)
#pragma unroll
            for (int j = 0; j < 8; j++) s_reg[i][j] = 0.f;

#pragma unroll
        for (int c4 = 0; c4 < Dh / 4; c4++) {
            float4 a[4], bb[8];
#pragma unroll
            for (int i = 0; i < 4; i++)
                a[i] = *(const float4*)&q_sh[(row_base + i) * SSTR + c4 * 4];
#pragma unroll
            for (int j = 0; j < 8; j++)
                bb[j] = *(const float4*)&k_sh[(col_base + j) * SSTR + c4 * 4];
#pragma unroll
            for (int i = 0; i < 4; i++)
#pragma unroll
                for (int j = 0; j < 8; j++) {
                    s_reg[i][j] += a[i].x * bb[j].x;
                    s_reg[i][j] += a[i].y * bb[j].y;
                    s_reg[i][j] += a[i].z * bb[j].z;
                    s_reg[i][j] += a[i].w * bb[j].w;
                }
        }

        // ---- mask, online softmax update ----
#pragma unroll
        for (int i = 0; i < 4; i++) {
            const int t_glob = m0 + row_base + i;
            float mx = -1e30f;
#pragma unroll
            for (int j = 0; j < 8; j++) {
                const int s_glob = s0 + col_base + j;
                const bool masked = (s_glob > t_glob) || (s_glob >= L);
                const float val = masked ? -1e30f : s_reg[i][j] * scale;
                s_reg[i][j] = val;
                mx = fmaxf(mx, val);
            }
            mx = fmaxf(mx, __shfl_xor_sync(0xffffffffu, mx, 1));
            mx = fmaxf(mx, __shfl_xor_sync(0xffffffffu, mx, 2));
            mx = fmaxf(mx, __shfl_xor_sync(0xffffffffu, mx, 4));
            const float m_new = fmaxf(m_i[i], mx);
            const float corr = __expf(m_i[i] - m_new);
            float sum = 0.f;
#pragma unroll
            for (int j = 0; j < 8; j++) {
                const float p = __expf(s_reg[i][j] - m_new);
                s_reg[i][j] = p;
                sum += p;
            }
            sum += __shfl_xor_sync(0xffffffffu, sum, 1);
            sum += __shfl_xor_sync(0xffffffffu, sum, 2);
            sum += __shfl_xor_sync(0xffffffffu, sum, 4);
            l_i[i] = l_i[i] * corr + sum;
            m_i[i] = m_new;
#pragma unroll
            for (int j = 0; j < 8; j++) acc[i][j] *= corr;
        }

        // ---- P -> shared ----
#pragma unroll
        for (int i = 0; i < 4; i++) {
            *(float4*)&p_sh[(row_base + i) * SSTR + col_base] =
                make_float4(s_reg[i][0], s_reg[i][1], s_reg[i][2], s_reg[i][3]);
            *(float4*)&p_sh[(row_base + i) * SSTR + col_base + 4] =
                make_float4(s_reg[i][4], s_reg[i][5], s_reg[i][6], s_reg[i][7]);
        }
        __syncthreads();

        // ---- O += P @ V ----
        for (int s = 0; s < BN; s++) {
            float pr[4];
#pragma unroll
            for (int i = 0; i < 4; i++) pr[i] = p_sh[(row_base + i) * SSTR + s];
            const float4 v0 = *(const float4*)&v_sh[s * SSTR + col_base];
            const float4 v1 = *(const float4*)&v_sh[s * SSTR + col_base + 4];
#pragma unroll
            for (int i = 0; i < 4; i++) {
                acc[i][0] += pr[i] * v0.x;
                acc[i][1] += pr[i] * v0.y;
                acc[i][2] += pr[i] * v0.z;
                acc[i][3] += pr[i] * v0.w;
                acc[i][4] += pr[i] * v1.x;
                acc[i][5] += pr[i] * v1.y;
                acc[i][6] += pr[i] * v1.z;
                acc[i][7] += pr[i] * v1.w;
            }
        }
    }

    // ---- normalize and write to scratch [B, T, H*Dh] ----
#pragma unroll
    for (int i = 0; i < 4; i++) {
        const float inv = 1.f / l_i[i];
        const int t_glob = m0 + row_base + i;
        float* dst = &g_attn[((size_t)(b * T_LEN + t_glob)) * STATE + h * Dh + col_base];
        *(float4*)dst = make_float4(acc[i][0] * inv, acc[i][1] * inv,
                                    acc[i][2] * inv, acc[i][3] * inv);
        *(float4*)(dst + 4) = make_float4(acc[i][4] * inv, acc[i][5] * inv,
                                          acc[i][6] * inv, acc[i][7] * inv);
    }
}

// ---------------------------------------------------------------------------
// Merge GEMM: out[4096,512] = g_attn[4096,512] @ W^T   (W is [512,512] row-major)
// 128x128x8 tiles, 256 threads, 8x8 microtile per thread.
// ---------------------------------------------------------------------------
__global__ void merge_kernel(const float* __restrict__ W, float* __restrict__ out)
{
    __shared__ __align__(16) float x_sh[8][132];
    __shared__ __align__(16) float w_sh[8][132];

    const int tid = threadIdx.x;        // 256
    const int j0 = blockIdx.x * 128;
    const int i0 = blockIdx.y * 128;
    const int ty = tid >> 4;            // 0..15
    const int tx = tid & 15;            // 0..15

    float c[8][8];
#pragma unroll
    for (int i = 0; i < 8; i++)
#pragma unroll
        for (int j = 0; j < 8; j++) c[i][j] = 0.f;

    for (int k0 = 0; k0 < STATE; k0 += 8) {
        __syncthreads();
        for (int t = tid; t < 1024; t += 256) {
            const int r = t >> 3, cc = t & 7;
            x_sh[cc][r] = g_attn[(size_t)(i0 + r) * STATE + k0 + cc];
            w_sh[cc][r] = W[(size_t)(j0 + r) * STATE + k0 + cc];
        }
        __syncthreads();
#pragma unroll
        for (int kk = 0; kk < 8; kk++) {
            float a[8], bb[8];
            *(float4*)&a[0]  = *(const float4*)&x_sh[kk][ty * 8];
            *(float4*)&a[4]  = *(const float4*)&x_sh[kk][ty * 8 + 4];
            *(float4*)&bb[0] = *(const float4*)&w_sh[kk][tx * 8];
            *(float4*)&bb[4] = *(const float4*)&w_sh[kk][tx * 8 + 4];
#pragma unroll
            for (int i = 0; i < 8; i++)
#pragma unroll
                for (int j = 0; j < 8; j++) c[i][j] += a[i] * bb[j];
        }
    }

#pragma unroll
    for (int i = 0; i < 8; i++) {
        float* dst = out + (size_t)(i0 + ty * 8 + i) * STATE + j0 + tx * 8;
        *(float4*)dst       = make_float4(c[i][0], c[i][1], c[i][2], c[i][3]);
        *(float4*)(dst + 4) = make_float4(c[i][4], c[i][5], c[i][6], c[i][7]);
    }
}

// ---------------------------------------------------------------------------
// Launch: inputs are q, k, v, position_mask (unused: deterministically causal),
// src_length_mask (int32 bool), W_merge.
// ---------------------------------------------------------------------------
extern "C" void kernel_launch(void* const* d_in, const int* in_sizes, int n_in,
                              void* d_out, int out_size)
{
    const float* q = (const float*)d_in[0];
    const float* k = (const float*)d_in[1];
    const float* v = (const float*)d_in[2];
    const int* lenmask = (const int*)d_in[4];
    const float* W = (const float*)d_in[5];
    float* out = (float*)d_out;

    const int smem = 4 * BM * SSTR * (int)sizeof(float);   // ~68 KB
    cudaFuncSetAttribute(attn_kernel, cudaFuncAttributeMaxDynamicSharedMemorySize, smem);

    attn_kernel<<<dim3(T_LEN / BM, BHn), NTHREADS, smem>>>(q, k, v, lenmask);
    merge_kernel<<<dim3(STATE / 128, (Bb * T_LEN) / 128), 256>>>(W, out);
}

// round 4
// speedup vs baseline: 3.1233x; 3.1233x over previous
#include <cuda_runtime.h>
#include <cuda_bf16.h>
#include <cstdint>

#define T_LEN   2048
#define Dh      64
#define Hh      8
#define Bb      2
#define BHn     16
#define STATE   512
#define BM      64
#define BN      64
#define NTHREADS 128

// Scratch: attention output in [B, T, H*Dh] layout (8 MB)
__device__ float g_attn[(size_t)Bb * T_LEN * STATE];

// bf16 hi/lo split of a pair of floats -> packed b32 (low half = first arg)
__device__ __forceinline__ void split2(float x, float y, uint32_t& h, uint32_t& l)
{
    __nv_bfloat162 hh = __floats2bfloat162_rn(x, y);
    float rx = x - __bfloat162float(hh.x);
    float ry = y - __bfloat162float(hh.y);
    __nv_bfloat162 ll = __floats2bfloat162_rn(rx, ry);
    h = *reinterpret_cast<uint32_t*>(&hh);
    l = *reinterpret_cast<uint32_t*>(&ll);
}

#define MMA_BF16(c, a, b0, b1)                                                  \
    asm volatile(                                                               \
        "mma.sync.aligned.m16n8k16.row.col.f32.bf16.bf16.f32 "                  \
        "{%0,%1,%2,%3}, {%4,%5,%6,%7}, {%8,%9}, {%0,%1,%2,%3};"                 \
        : "+f"((c)[0]), "+f"((c)[1]), "+f"((c)[2]), "+f"((c)[3])                \
        : "r"((a)[0]), "r"((a)[1]), "r"((a)[2]), "r"((a)[3]),                   \
          "r"(b0), "r"(b1))

// ---------------------------------------------------------------------------
// Flash attention, bf16-split tensor-core path.
// Grid: (32, 16). 128 threads = 4 warps; warp w owns rows [w*16, w*16+16).
// ---------------------------------------------------------------------------
__global__ void __launch_bounds__(NTHREADS, 2)
attn_kernel(const float* __restrict__ q,
            const float* __restrict__ k,
            const float* __restrict__ v,
            const int* __restrict__ lenmask)
{
    __shared__ __align__(16) __nv_bfloat16 Kh[BN][72];
    __shared__ __align__(16) __nv_bfloat16 Kl[BN][72];
    __shared__ __align__(16) __nv_bfloat16 Vth[Dh][72];   // V transposed [d][s]
    __shared__ __align__(16) __nv_bfloat16 Vtl[Dh][72];
    __shared__ int sh_len;

    const int tid  = threadIdx.x;
    const int lane = tid & 31;
    const int w    = tid >> 5;
    const int bh   = blockIdx.y;
    const int b    = bh >> 3;
    const int h    = bh & 7;
    const int m0   = (31 - blockIdx.x) * BM;    // long CTAs launch first

    // ---- per-batch valid length ----
    if (tid == 0) sh_len = 0;
    __syncthreads();
    {
        int cnt = 0;
        const int* lm = lenmask + (size_t)b * T_LEN;
        for (int s = tid; s < T_LEN; s += NTHREADS) cnt += (lm[s] == 0);
        cnt += __shfl_xor_sync(0xffffffffu, cnt, 1);
        cnt += __shfl_xor_sync(0xffffffffu, cnt, 2);
        cnt += __shfl_xor_sync(0xffffffffu, cnt, 4);
        cnt += __shfl_xor_sync(0xffffffffu, cnt, 8);
        cnt += __shfl_xor_sync(0xffffffffu, cnt, 16);
        if (lane == 0) atomicAdd(&sh_len, cnt);
    }

    const int r    = lane >> 2;        // 0..7
    const int qoff = (lane & 3) * 2;   // 0,2,4,6
    const int t0   = m0 + w * 16 + r;  // global query rows owned by this thread
    const int t1   = t0 + 8;

    // ---- Q fragments (hi/lo), resident in registers ----
    uint32_t qa_h[4][4], qa_l[4][4];
    {
        const float* qb = q + ((size_t)bh * T_LEN) * Dh;
#pragma unroll
        for (int ks = 0; ks < 4; ks++) {
            const int c = ks * 16 + qoff;
            const float2 x0 = *(const float2*)(qb + (size_t)t0 * Dh + c);
            const float2 x1 = *(const float2*)(qb + (size_t)t1 * Dh + c);
            const float2 x2 = *(const float2*)(qb + (size_t)t0 * Dh + c + 8);
            const float2 x3 = *(const float2*)(qb + (size_t)t1 * Dh + c + 8);
            split2(x0.x, x0.y, qa_h[ks][0], qa_l[ks][0]);
            split2(x1.x, x1.y, qa_h[ks][1], qa_l[ks][1]);
            split2(x2.x, x2.y, qa_h[ks][2], qa_l[ks][2]);
            split2(x3.x, x3.y, qa_h[ks][3], qa_l[ks][3]);
        }
    }
    __syncthreads();
    const int L = sh_len;

    float m_i0 = -1e30f, m_i1 = -1e30f, l_i0 = 0.f, l_i1 = 0.f;
    float o_c[8][4];
#pragma unroll
    for (int dt = 0; dt < 8; dt++)
#pragma unroll
        for (int e = 0; e < 4; e++) o_c[dt][e] = 0.f;

    const float scale = 0.125f;
    const int s_end = m0 + BM;

    for (int s0 = 0; s0 < s_end; s0 += BN) {
        if (s0 >= L) break;
        __syncthreads();

        // ---- fill K (row-major) and V (transposed) bf16 hi/lo tiles ----
        {
            const float4* kg = (const float4*)(k + ((size_t)bh * T_LEN + s0) * Dh);
            const float4* vg = (const float4*)(v + ((size_t)bh * T_LEN + s0) * Dh);
            for (int i = tid; i < BN * (Dh / 4); i += NTHREADS) {
                const int row = i >> 4, c4 = i & 15;
                const float4 kk4 = kg[row * 16 + c4];
                uint32_t h0, l0, h1, l1;
                split2(kk4.x, kk4.y, h0, l0);
                split2(kk4.z, kk4.w, h1, l1);
                *(uint32_t*)&Kh[row][c4 * 4]     = h0;
                *(uint32_t*)&Kh[row][c4 * 4 + 2] = h1;
                *(uint32_t*)&Kl[row][c4 * 4]     = l0;
                *(uint32_t*)&Kl[row][c4 * 4 + 2] = l1;

                const float4 vv4 = vg[row * 16 + c4];
                const float vals[4] = { vv4.x, vv4.y, vv4.z, vv4.w };
#pragma unroll
                for (int j = 0; j < 4; j++) {
                    const __nv_bfloat16 vh = __float2bfloat16(vals[j]);
                    const __nv_bfloat16 vl = __float2bfloat16(vals[j] - __bfloat162float(vh));
                    Vth[c4 * 4 + j][row] = vh;
                    Vtl[c4 * 4 + j][row] = vl;
                }
            }
        }
        __syncthreads();

        // ---- S = Q K^T (3-term bf16 split) ----
        float s_c[8][4];
#pragma unroll
        for (int nt = 0; nt < 8; nt++)
#pragma unroll
            for (int e = 0; e < 4; e++) s_c[nt][e] = 0.f;

#pragma unroll
        for (int ks = 0; ks < 4; ks++) {
            const int dbase = ks * 16 + qoff;
#pragma unroll
            for (int nt = 0; nt < 8; nt++) {
                const int j = nt * 8 + r;
                const uint32_t bh0 = *(const uint32_t*)&Kh[j][dbase];
                const uint32_t bh1 = *(const uint32_t*)&Kh[j][dbase + 8];
                const uint32_t bl0 = *(const uint32_t*)&Kl[j][dbase];
                const uint32_t bl1 = *(const uint32_t*)&Kl[j][dbase + 8];
                MMA_BF16(s_c[nt], qa_h[ks], bh0, bh1);
                MMA_BF16(s_c[nt], qa_h[ks], bl0, bl1);
                MMA_BF16(s_c[nt], qa_l[ks], bh0, bh1);
            }
        }

        // ---- mask + online softmax ----
        float mx0 = -1e30f, mx1 = -1e30f;
#pragma unroll
        for (int nt = 0; nt < 8; nt++) {
#pragma unroll
            for (int e = 0; e < 2; e++) {
                const int sg = s0 + nt * 8 + qoff + e;
                const bool lenm = (sg >= L);
                float v0 = (lenm || sg > t0) ? -1e30f : s_c[nt][e] * scale;
                float v1 = (lenm || sg > t1) ? -1e30f : s_c[nt][2 + e] * scale;
                s_c[nt][e] = v0;  s_c[nt][2 + e] = v1;
                mx0 = fmaxf(mx0, v0);  mx1 = fmaxf(mx1, v1);
            }
        }
        mx0 = fmaxf(mx0, __shfl_xor_sync(0xffffffffu, mx0, 1));
        mx0 = fmaxf(mx0, __shfl_xor_sync(0xffffffffu, mx0, 2));
        mx1 = fmaxf(mx1, __shfl_xor_sync(0xffffffffu, mx1, 1));
        mx1 = fmaxf(mx1, __shfl_xor_sync(0xffffffffu, mx1, 2));

        const float mn0 = fmaxf(m_i0, mx0), mn1 = fmaxf(m_i1, mx1);
        const float corr0 = __expf(m_i0 - mn0), corr1 = __expf(m_i1 - mn1);
        float sum0 = 0.f, sum1 = 0.f;
#pragma unroll
        for (int nt = 0; nt < 8; nt++) {
#pragma unroll
            for (int e = 0; e < 2; e++) {
                const float p0 = __expf(s_c[nt][e] - mn0);
                const float p1 = __expf(s_c[nt][2 + e] - mn1);
                s_c[nt][e] = p0;  s_c[nt][2 + e] = p1;
                sum0 += p0;  sum1 += p1;
            }
        }
        sum0 += __shfl_xor_sync(0xffffffffu, sum0, 1);
        sum0 += __shfl_xor_sync(0xffffffffu, sum0, 2);
        sum1 += __shfl_xor_sync(0xffffffffu, sum1, 1);
        sum1 += __shfl_xor_sync(0xffffffffu, sum1, 2);
        l_i0 = l_i0 * corr0 + sum0;  m_i0 = mn0;
        l_i1 = l_i1 * corr1 + sum1;  m_i1 = mn1;
#pragma unroll
        for (int dt = 0; dt < 8; dt++) {
            o_c[dt][0] *= corr0;  o_c[dt][1] *= corr0;
            o_c[dt][2] *= corr1;  o_c[dt][3] *= corr1;
        }

        // ---- pack P (C-frag -> A-frag identity, register-only) ----
        uint32_t pa_h[4][4], pa_l[4][4];
#pragma unroll
        for (int g = 0; g < 4; g++) {
            split2(s_c[2 * g][0],     s_c[2 * g][1],     pa_h[g][0], pa_l[g][0]);
            split2(s_c[2 * g][2],     s_c[2 * g][3],     pa_h[g][1], pa_l[g][1]);
            split2(s_c[2 * g + 1][0], s_c[2 * g + 1][1], pa_h[g][2], pa_l[g][2]);
            split2(s_c[2 * g + 1][2], s_c[2 * g + 1][3], pa_h[g][3], pa_l[g][3]);
        }

        // ---- O += P V (3-term bf16 split), V^T frags from smem ----
#pragma unroll
        for (int g = 0; g < 4; g++) {
            const int sb = g * 16 + qoff;
#pragma unroll
            for (int dt = 0; dt < 8; dt++) {
                const int d = dt * 8 + r;
                const uint32_t vh0 = *(const uint32_t*)&Vth[d][sb];
                const uint32_t vh1 = *(const uint32_t*)&Vth[d][sb + 8];
                const uint32_t vl0 = *(const uint32_t*)&Vtl[d][sb];
                const uint32_t vl1 = *(const uint32_t*)&Vtl[d][sb + 8];
                MMA_BF16(o_c[dt], pa_h[g], vh0, vh1);
                MMA_BF16(o_c[dt], pa_h[g], vl0, vl1);
                MMA_BF16(o_c[dt], pa_l[g], vh0, vh1);
            }
        }
    }

    // ---- normalize + write scratch [B, T, H*Dh] ----
    const float inv0 = 1.f / l_i0, inv1 = 1.f / l_i1;
    float* ob0 = &g_attn[((size_t)(b * T_LEN + t0)) * STATE + h * Dh + qoff];
    float* ob1 = &g_attn[((size_t)(b * T_LEN + t1)) * STATE + h * Dh + qoff];
#pragma unroll
    for (int dt = 0; dt < 8; dt++) {
        *(float2*)(ob0 + dt * 8) = make_float2(o_c[dt][0] * inv0, o_c[dt][1] * inv0);
        *(float2*)(ob1 + dt * 8) = make_float2(o_c[dt][2] * inv1, o_c[dt][3] * inv1);
    }
}

// ---------------------------------------------------------------------------
// Merge GEMM: out[4096,512] = g_attn @ W^T. 64x64 tiles, 128 threads,
// k-tile 16, 4x8 microtile. Grid (8, 64) = 512 CTAs.
// ---------------------------------------------------------------------------
__global__ void __launch_bounds__(128) merge_kernel(const float* __restrict__ W,
                                                    float* __restrict__ out)
{
    __shared__ __align__(16) float x_sh[16][68];
    __shared__ __align__(16) float w_sh[16][68];

    const int tid = threadIdx.x;
    const int n0 = blockIdx.x * 64;
    const int m0 = blockIdx.y * 64;
    const int tm = tid >> 3;        // 0..15
    const int tn = tid & 7;         // 0..7

    float acc[4][8];
#pragma unroll
    for (int i = 0; i < 4; i++)
#pragma unroll
        for (int j = 0; j < 8; j++) acc[i][j] = 0.f;

    for (int k0 = 0; k0 < STATE; k0 += 16) {
        __syncthreads();
        for (int t = tid; t < 64 * 16; t += 128) {
            const int rr = t >> 4, cc = t & 15;
            x_sh[cc][rr] = g_attn[(size_t)(m0 + rr) * STATE + k0 + cc];
            w_sh[cc][rr] = W[(size_t)(n0 + rr) * STATE + k0 + cc];
        }
        __syncthreads();
#pragma unroll
        for (int kk = 0; kk < 16; kk++) {
            const float4 a4 = *(const float4*)&x_sh[kk][tm * 4];
            const float4 b0 = *(const float4*)&w_sh[kk][tn * 8];
            const float4 b1 = *(const float4*)&w_sh[kk][tn * 8 + 4];
            const float a[4] = { a4.x, a4.y, a4.z, a4.w };
            const float bb[8] = { b0.x, b0.y, b0.z, b0.w, b1.x, b1.y, b1.z, b1.w };
#pragma unroll
            for (int i = 0; i < 4; i++)
#pragma unroll
                for (int j = 0; j < 8; j++) acc[i][j] += a[i] * bb[j];
        }
    }

#pragma unroll
    for (int i = 0; i < 4; i++) {
        float* dst = out + (size_t)(m0 + tm * 4 + i) * STATE + n0 + tn * 8;
        *(float4*)dst       = make_float4(acc[i][0], acc[i][1], acc[i][2], acc[i][3]);
        *(float4*)(dst + 4) = make_float4(acc[i][4], acc[i][5], acc[i][6], acc[i][7]);
    }
}

extern "C" void kernel_launch(void* const* d_in, const int* in_sizes, int n_in,
                              void* d_out, int out_size)
{
    const float* q = (const float*)d_in[0];
    const float* k = (const float*)d_in[1];
    const float* v = (const float*)d_in[2];
    const int* lenmask = (const int*)d_in[4];
    const float* W = (const float*)d_in[5];
    float* out = (float*)d_out;

    attn_kernel<<<dim3(T_LEN / BM, BHn), NTHREADS>>>(q, k, v, lenmask);
    merge_kernel<<<dim3(STATE / 64, (Bb * T_LEN) / 64), 128>>>(W, out);
}

// round 5
// speedup vs baseline: 10.3490x; 3.3135x over previous
#include <cuda_runtime.h>
#include <cuda_bf16.h>
#include <cstdint>

#define T_LEN   2048
#define Dh      64
#define Hh      8
#define Bb      2
#define BHn     16
#define STATE   512
#define BM      64
#define BN      64
#define NTHREADS 128

typedef __nv_bfloat16 bf16;

// Pre-split operands (device scratch)
__device__ bf16 g_Kh[(size_t)BHn * T_LEN * Dh];
__device__ bf16 g_Kl[(size_t)BHn * T_LEN * Dh];
__device__ bf16 g_Vth[(size_t)BHn * Dh * T_LEN];   // transposed [bh][d][s]
__device__ bf16 g_Vtl[(size_t)BHn * Dh * T_LEN];
__device__ bf16 g_Wh[(size_t)STATE * STATE];
__device__ bf16 g_Wl[(size_t)STATE * STATE];
// Attention output scratch, bf16 hi/lo, [B, T, STATE]
__device__ bf16 g_Xh[(size_t)Bb * T_LEN * STATE];
__device__ bf16 g_Xl[(size_t)Bb * T_LEN * STATE];

__device__ __forceinline__ void split2(float x, float y, uint32_t& h, uint32_t& l)
{
    __nv_bfloat162 hh = __floats2bfloat162_rn(x, y);
    float rx = x - __bfloat162float(hh.x);
    float ry = y - __bfloat162float(hh.y);
    __nv_bfloat162 ll = __floats2bfloat162_rn(rx, ry);
    h = *reinterpret_cast<uint32_t*>(&hh);
    l = *reinterpret_cast<uint32_t*>(&ll);
}

#define MMA_BF16(c, a, b0, b1)                                                  \
    asm volatile(                                                               \
        "mma.sync.aligned.m16n8k16.row.col.f32.bf16.bf16.f32 "                  \
        "{%0,%1,%2,%3}, {%4,%5,%6,%7}, {%8,%9}, {%0,%1,%2,%3};"                 \
        : "+f"((c)[0]), "+f"((c)[1]), "+f"((c)[2]), "+f"((c)[3])                \
        : "r"((a)[0]), "r"((a)[1]), "r"((a)[2]), "r"((a)[3]),                   \
          "r"(b0), "r"(b1))

// ---------------------------------------------------------------------------
// Pre-pass: elementwise fp32 -> bf16 hi/lo split (K and W)
// ---------------------------------------------------------------------------
__global__ void split_map(const float* __restrict__ src,
                          bf16* __restrict__ dh, bf16* __restrict__ dl, int n2)
{
    const int i = blockIdx.x * blockDim.x + threadIdx.x;
    if (i < n2) {
        const float2 x = ((const float2*)src)[i];
        uint32_t h, l;
        split2(x.x, x.y, h, l);
        ((uint32_t*)dh)[i] = h;
        ((uint32_t*)dl)[i] = l;
    }
}

// ---------------------------------------------------------------------------
// Pre-pass: V -> transposed bf16 hi/lo [bh][d][s]
// ---------------------------------------------------------------------------
__global__ void __launch_bounds__(128) prep_v(const float* __restrict__ v)
{
    __shared__ bf16 Th[64][72];
    __shared__ bf16 Tl[64][72];
    const int tid = threadIdx.x;
    const int s0 = blockIdx.x * 64;
    const int bh = blockIdx.y;

    for (int i = tid; i < 64 * 16; i += 128) {
        const int row = i >> 4, c4 = i & 15;
        const float4 x = *(const float4*)(v + ((size_t)bh * T_LEN + s0 + row) * Dh + c4 * 4);
        const float vals[4] = { x.x, x.y, x.z, x.w };
#pragma unroll
        for (int j = 0; j < 4; j++) {
            const bf16 vh = __float2bfloat16(vals[j]);
            Th[c4 * 4 + j][row] = vh;
            Tl[c4 * 4 + j][row] = __float2bfloat16(vals[j] - __bfloat162float(vh));
        }
    }
    __syncthreads();
    for (int i = tid; i < 64 * 8; i += 128) {
        const int d = i >> 3, c = i & 7;
        const size_t base = ((size_t)bh * Dh + d) * T_LEN + s0;
        *(uint4*)(g_Vth + base + c * 8) = *(const uint4*)&Th[d][c * 8];
        *(uint4*)(g_Vtl + base + c * 8) = *(const uint4*)&Tl[d][c * 8];
    }
}

// ---------------------------------------------------------------------------
// Flash attention, bf16-split tensor cores, pre-split K/V tiles.
// Grid: (32, 16). 128 threads = 4 warps; warp w owns rows [w*16, w*16+16).
// ---------------------------------------------------------------------------
__global__ void __launch_bounds__(NTHREADS, 2)
attn_kernel(const float* __restrict__ q, const int* __restrict__ lenmask)
{
    __shared__ __align__(16) bf16 Kh[BN][72];
    __shared__ __align__(16) bf16 Kl[BN][72];
    __shared__ __align__(16) bf16 Vth[Dh][72];
    __shared__ __align__(16) bf16 Vtl[Dh][72];
    __shared__ int sh_len;

    const int tid  = threadIdx.x;
    const int lane = tid & 31;
    const int w    = tid >> 5;
    const int bh   = blockIdx.y;
    const int b    = bh >> 3;
    const int h    = bh & 7;
    const int m0   = (31 - blockIdx.x) * BM;    // long CTAs launch first

    if (tid == 0) sh_len = 0;
    __syncthreads();
    {
        int cnt = 0;
        const int* lm = lenmask + (size_t)b * T_LEN;
        for (int s = tid; s < T_LEN; s += NTHREADS) cnt += (lm[s] == 0);
        cnt += __shfl_xor_sync(0xffffffffu, cnt, 1);
        cnt += __shfl_xor_sync(0xffffffffu, cnt, 2);
        cnt += __shfl_xor_sync(0xffffffffu, cnt, 4);
        cnt += __shfl_xor_sync(0xffffffffu, cnt, 8);
        cnt += __shfl_xor_sync(0xffffffffu, cnt, 16);
        if (lane == 0) atomicAdd(&sh_len, cnt);
    }

    const int r    = lane >> 2;
    const int qoff = (lane & 3) * 2;
    const int t0   = m0 + w * 16 + r;
    const int t1   = t0 + 8;

    // Q fragments (hi/lo) in registers — split once
    uint32_t qa_h[4][4], qa_l[4][4];
    {
        const float* qb = q + ((size_t)bh * T_LEN) * Dh;
#pragma unroll
        for (int ks = 0; ks < 4; ks++) {
            const int c = ks * 16 + qoff;
            const float2 x0 = *(const float2*)(qb + (size_t)t0 * Dh + c);
            const float2 x1 = *(const float2*)(qb + (size_t)t1 * Dh + c);
            const float2 x2 = *(const float2*)(qb + (size_t)t0 * Dh + c + 8);
            const float2 x3 = *(const float2*)(qb + (size_t)t1 * Dh + c + 8);
            split2(x0.x, x0.y, qa_h[ks][0], qa_l[ks][0]);
            split2(x1.x, x1.y, qa_h[ks][1], qa_l[ks][1]);
            split2(x2.x, x2.y, qa_h[ks][2], qa_l[ks][2]);
            split2(x3.x, x3.y, qa_h[ks][3], qa_l[ks][3]);
        }
    }
    __syncthreads();
    const int L = sh_len;

    float m_i0 = -1e30f, m_i1 = -1e30f, l_i0 = 0.f, l_i1 = 0.f;
    float o_c[8][4];
#pragma unroll
    for (int dt = 0; dt < 8; dt++)
#pragma unroll
        for (int e = 0; e < 4; e++) o_c[dt][e] = 0.f;

    const float scale = 0.125f;
    const int s_end = m0 + BM;

    for (int s0 = 0; s0 < s_end; s0 += BN) {
        if (s0 >= L) break;
        __syncthreads();

        // ---- pure uint4 copies of pre-split tiles ----
        {
            const uint4* kh = (const uint4*)(g_Kh + ((size_t)bh * T_LEN + s0) * Dh);
            const uint4* kl = (const uint4*)(g_Kl + ((size_t)bh * T_LEN + s0) * Dh);
            for (int i = tid; i < 512; i += NTHREADS) {
                const int row = i >> 3, c = i & 7;
                *(uint4*)&Kh[row][c * 8] = kh[i];
                *(uint4*)&Kl[row][c * 8] = kl[i];
                const size_t vb = ((size_t)bh * Dh + row) * T_LEN + s0;
                *(uint4*)&Vth[row][c * 8] = *(const uint4*)(g_Vth + vb + c * 8);
                *(uint4*)&Vtl[row][c * 8] = *(const uint4*)(g_Vtl + vb + c * 8);
            }
        }
        __syncthreads();

        // ---- S = Q K^T (3-term bf16 split) ----
        float s_c[8][4];
#pragma unroll
        for (int nt = 0; nt < 8; nt++)
#pragma unroll
            for (int e = 0; e < 4; e++) s_c[nt][e] = 0.f;

#pragma unroll
        for (int ks = 0; ks < 4; ks++) {
            const int dbase = ks * 16 + qoff;
#pragma unroll
            for (int nt = 0; nt < 8; nt++) {
                const int j = nt * 8 + r;
                const uint32_t bh0 = *(const uint32_t*)&Kh[j][dbase];
                const uint32_t bh1 = *(const uint32_t*)&Kh[j][dbase + 8];
                const uint32_t bl0 = *(const uint32_t*)&Kl[j][dbase];
                const uint32_t bl1 = *(const uint32_t*)&Kl[j][dbase + 8];
                MMA_BF16(s_c[nt], qa_h[ks], bh0, bh1);
                MMA_BF16(s_c[nt], qa_h[ks], bl0, bl1);
                MMA_BF16(s_c[nt], qa_l[ks], bh0, bh1);
            }
        }

        // ---- mask + online softmax ----
        float mx0 = -1e30f, mx1 = -1e30f;
#pragma unroll
        for (int nt = 0; nt < 8; nt++) {
#pragma unroll
            for (int e = 0; e < 2; e++) {
                const int sg = s0 + nt * 8 + qoff + e;
                const bool lenm = (sg >= L);
                float v0 = (lenm || sg > t0) ? -1e30f : s_c[nt][e] * scale;
                float v1 = (lenm || sg > t1) ? -1e30f : s_c[nt][2 + e] * scale;
                s_c[nt][e] = v0;  s_c[nt][2 + e] = v1;
                mx0 = fmaxf(mx0, v0);  mx1 = fmaxf(mx1, v1);
            }
        }
        mx0 = fmaxf(mx0, __shfl_xor_sync(0xffffffffu, mx0, 1));
        mx0 = fmaxf(mx0, __shfl_xor_sync(0xffffffffu, mx0, 2));
        mx1 = fmaxf(mx1, __shfl_xor_sync(0xffffffffu, mx1, 1));
        mx1 = fmaxf(mx1, __shfl_xor_sync(0xffffffffu, mx1, 2));

        const float mn0 = fmaxf(m_i0, mx0), mn1 = fmaxf(m_i1, mx1);
        const float corr0 = __expf(m_i0 - mn0), corr1 = __expf(m_i1 - mn1);
        float sum0 = 0.f, sum1 = 0.f;
#pragma unroll
        for (int nt = 0; nt < 8; nt++) {
#pragma unroll
            for (int e = 0; e < 2; e++) {
                const float p0 = __expf(s_c[nt][e] - mn0);
                const float p1 = __expf(s_c[nt][2 + e] - mn1);
                s_c[nt][e] = p0;  s_c[nt][2 + e] = p1;
                sum0 += p0;  sum1 += p1;
            }
        }
        sum0 += __shfl_xor_sync(0xffffffffu, sum0, 1);
        sum0 += __shfl_xor_sync(0xffffffffu, sum0, 2);
        sum1 += __shfl_xor_sync(0xffffffffu, sum1, 1);
        sum1 += __shfl_xor_sync(0xffffffffu, sum1, 2);
        l_i0 = l_i0 * corr0 + sum0;  m_i0 = mn0;
        l_i1 = l_i1 * corr1 + sum1;  m_i1 = mn1;
#pragma unroll
        for (int dt = 0; dt < 8; dt++) {
            o_c[dt][0] *= corr0;  o_c[dt][1] *= corr0;
            o_c[dt][2] *= corr1;  o_c[dt][3] *= corr1;
        }

        // ---- pack P (register-only) ----
        uint32_t pa_h[4][4], pa_l[4][4];
#pragma unroll
        for (int g = 0; g < 4; g++) {
            split2(s_c[2 * g][0],     s_c[2 * g][1],     pa_h[g][0], pa_l[g][0]);
            split2(s_c[2 * g][2],     s_c[2 * g][3],     pa_h[g][1], pa_l[g][1]);
            split2(s_c[2 * g + 1][0], s_c[2 * g + 1][1], pa_h[g][2], pa_l[g][2]);
            split2(s_c[2 * g + 1][2], s_c[2 * g + 1][3], pa_h[g][3], pa_l[g][3]);
        }

        // ---- O += P V (3-term bf16 split) ----
#pragma unroll
        for (int g = 0; g < 4; g++) {
            const int sb = g * 16 + qoff;
#pragma unroll
            for (int dt = 0; dt < 8; dt++) {
                const int d = dt * 8 + r;
                const uint32_t vh0 = *(const uint32_t*)&Vth[d][sb];
                const uint32_t vh1 = *(const uint32_t*)&Vth[d][sb + 8];
                const uint32_t vl0 = *(const uint32_t*)&Vtl[d][sb];
                const uint32_t vl1 = *(const uint32_t*)&Vtl[d][sb + 8];
                MMA_BF16(o_c[dt], pa_h[g], vh0, vh1);
                MMA_BF16(o_c[dt], pa_h[g], vl0, vl1);
                MMA_BF16(o_c[dt], pa_l[g], vh0, vh1);
            }
        }
    }

    // ---- normalize + write bf16 hi/lo scratch [B, T, STATE] ----
    const float inv0 = 1.f / l_i0, inv1 = 1.f / l_i1;
    const size_t ob0 = ((size_t)(b * T_LEN + t0)) * STATE + h * Dh + qoff;
    const size_t ob1 = ((size_t)(b * T_LEN + t1)) * STATE + h * Dh + qoff;
#pragma unroll
    for (int dt = 0; dt < 8; dt++) {
        uint32_t h0, l0, h1, l1;
        split2(o_c[dt][0] * inv0, o_c[dt][1] * inv0, h0, l0);
        split2(o_c[dt][2] * inv1, o_c[dt][3] * inv1, h1, l1);
        *(uint32_t*)(g_Xh + ob0 + dt * 8) = h0;
        *(uint32_t*)(g_Xl + ob0 + dt * 8) = l0;
        *(uint32_t*)(g_Xh + ob1 + dt * 8) = h1;
        *(uint32_t*)(g_Xl + ob1 + dt * 8) = l1;
    }
}

// ---------------------------------------------------------------------------
// Merge GEMM on tensor cores: out[4096,512] = X @ W^T, X/W pre-split bf16.
// 64x64 tiles, 4 warps, k-chunks of 64. Grid (8, 64).
// ---------------------------------------------------------------------------
__global__ void __launch_bounds__(128) merge_kernel(float* __restrict__ out)
{
    __shared__ __align__(16) bf16 Xh[64][72];
    __shared__ __align__(16) bf16 Xl[64][72];
    __shared__ __align__(16) bf16 Wh[64][72];
    __shared__ __align__(16) bf16 Wl[64][72];

    const int tid  = threadIdx.x;
    const int lane = tid & 31;
    const int w    = tid >> 5;
    const int n0   = blockIdx.x * 64;
    const int m0   = blockIdx.y * 64;
    const int r    = lane >> 2;
    const int qoff = (lane & 3) * 2;

    float acc[8][4];
#pragma unroll
    for (int nt = 0; nt < 8; nt++)
#pragma unroll
        for (int e = 0; e < 4; e++) acc[nt][e] = 0.f;

    for (int k0 = 0; k0 < STATE; k0 += 64) {
        __syncthreads();
        for (int i = tid; i < 512; i += 128) {
            const int row = i >> 3, c = i & 7;
            const size_t xb = (size_t)(m0 + row) * STATE + k0;
            const size_t wb = (size_t)(n0 + row) * STATE + k0;
            *(uint4*)&Xh[row][c * 8] = *(const uint4*)(g_Xh + xb + c * 8);
            *(uint4*)&Xl[row][c * 8] = *(const uint4*)(g_Xl + xb + c * 8);
            *(uint4*)&Wh[row][c * 8] = *(const uint4*)(g_Wh + wb + c * 8);
            *(uint4*)&Wl[row][c * 8] = *(const uint4*)(g_Wl + wb + c * 8);
        }
        __syncthreads();

#pragma unroll
        for (int ks = 0; ks < 4; ks++) {
            const int c = ks * 16 + qoff;
            uint32_t a_h[4], a_l[4];
            a_h[0] = *(const uint32_t*)&Xh[w * 16 + r][c];
            a_h[1] = *(const uint32_t*)&Xh[w * 16 + r + 8][c];
            a_h[2] = *(const uint32_t*)&Xh[w * 16 + r][c + 8];
            a_h[3] = *(const uint32_t*)&Xh[w * 16 + r + 8][c + 8];
            a_l[0] = *(const uint32_t*)&Xl[w * 16 + r][c];
            a_l[1] = *(const uint32_t*)&Xl[w * 16 + r + 8][c];
            a_l[2] = *(const uint32_t*)&Xl[w * 16 + r][c + 8];
            a_l[3] = *(const uint32_t*)&Xl[w * 16 + r + 8][c + 8];
#pragma unroll
            for (int nt = 0; nt < 8; nt++) {
                const int j = nt * 8 + r;
                const uint32_t bh0 = *(const uint32_t*)&Wh[j][c];
                const uint32_t bh1 = *(const uint32_t*)&Wh[j][c + 8];
                const uint32_t bl0 = *(const uint32_t*)&Wl[j][c];
                const uint32_t bl1 = *(const uint32_t*)&Wl[j][c + 8];
                MMA_BF16(acc[nt], a_h, bh0, bh1);
                MMA_BF16(acc[nt], a_h, bl0, bl1);
                MMA_BF16(acc[nt], a_l, bh0, bh1);
            }
        }
    }

    const int mr0 = m0 + w * 16 + r;
#pragma unroll
    for (int nt = 0; nt < 8; nt++) {
        const int n = n0 + nt * 8 + qoff;
        *(float2*)(out + (size_t)mr0 * STATE + n)       = make_float2(acc[nt][0], acc[nt][1]);
        *(float2*)(out + (size_t)(mr0 + 8) * STATE + n) = make_float2(acc[nt][2], acc[nt][3]);
    }
}

extern "C" void kernel_launch(void* const* d_in, const int* in_sizes, int n_in,
                              void* d_out, int out_size)
{
    const float* q = (const float*)d_in[0];
    const float* k = (const float*)d_in[1];
    const float* v = (const float*)d_in[2];
    const int* lenmask = (const int*)d_in[4];
    const float* W = (const float*)d_in[5];
    float* out = (float*)d_out;

    bf16 *kh, *kl, *wh, *wl;
    cudaGetSymbolAddress((void**)&kh, g_Kh);
    cudaGetSymbolAddress((void**)&kl, g_Kl);
    cudaGetSymbolAddress((void**)&wh, g_Wh);
    cudaGetSymbolAddress((void**)&wl, g_Wl);

    // Pre-split K and W (pairs of floats per thread)
    {
        const int nk2 = BHn * T_LEN * Dh / 2;       // 1,048,576
        split_map<<<(nk2 + 255) / 256, 256>>>(k, kh, kl, nk2);
        const int nw2 = STATE * STATE / 2;          // 131,072
        split_map<<<(nw2 + 255) / 256, 256>>>(W, wh, wl, nw2);
    }
    prep_v<<<dim3(T_LEN / 64, BHn), 128>>>(v);

    attn_kernel<<<dim3(T_LEN / BM, BHn), NTHREADS>>>(q, lenmask);
    merge_kernel<<<dim3(STATE / 64, (Bb * T_LEN) / 64), 128>>>(out);
}